// round 3
// baseline (speedup 1.0000x reference)
#include <cuda_runtime.h>

#define IMG_H 512
#define IMG_W 512
#define TILE_H 32
#define NTHREADS 128   // 4 warps, each warp owns a 128-col strip

__device__ __forceinline__ int reflr(int g) {
    // reflect-101: -1 -> 1, -2 -> 2, 512 -> 510, 513 -> 509
    g = g < 0 ? -g : g;
    if (g >= IMG_H) g = 2 * IMG_H - 2 - g;
    return g;
}

// Load one source row's worth for this thread: main float4 + predicated edge halos.
__device__ __forceinline__ void loadRow(const float* __restrict__ rowp, int c0,
                                        bool isL, bool isR,
                                        int lc0, int lc1, int rc0, int rc1,
                                        float4& m, float2& l, float2& r)
{
    m = *reinterpret_cast<const float4*>(rowp + c0);
    if (isL) { l.x = rowp[lc0]; l.y = rowp[lc1]; }
    if (isR) { r.x = rowp[rc0]; r.y = rowp[rc1]; }
}

// Horizontal 5-tap given this thread's vertical sums v (cols c..c+3) and
// edge-lane halo vertical sums vl (cols c-2,c-1) / vr (cols c+4,c+5).
__device__ __forceinline__ float4 hstep(float4 v, float2 vl, float2 vr, int lane)
{
    float a = __shfl_up_sync(0xFFFFFFFFu, v.z, 1);    // col c-2
    float b = __shfl_up_sync(0xFFFFFFFFu, v.w, 1);    // col c-1
    float c = __shfl_down_sync(0xFFFFFFFFu, v.x, 1);  // col c+4
    float d = __shfl_down_sync(0xFFFFFFFFu, v.y, 1);  // col c+5
    if (lane == 0)  { a = vl.x; b = vl.y; }
    if (lane == 31) { c = vr.x; d = vr.y; }
    const float inv25 = 1.0f / 25.0f;
    float s01 = v.x + v.y;
    float s23 = v.z + v.w;
    float4 o;
    o.x = (a + b + s01 + v.z) * inv25;
    o.y = (b + s01 + s23)     * inv25;
    o.z = (s01 + s23 + c)     * inv25;
    o.w = (v.y + s23 + c + d) * inv25;
    return o;
}

__global__ __launch_bounds__(NTHREADS)
void smooth5_kernel(const float* __restrict__ in, float* __restrict__ out)
{
    const int tid   = threadIdx.x;
    const int lane  = tid & 31;
    const int c0    = (tid >> 5) * 128 + lane * 4;
    const int plane = blockIdx.y;
    const int row0  = blockIdx.x * TILE_H;

    const float* ip = in  + (size_t)plane * (IMG_H * IMG_W);
    float*       op = out + (size_t)plane * (IMG_H * IMG_W);

    const bool isL = (lane == 0);
    const bool isR = (lane == 31);
    // Left halo source cols (c-2, c-1); reflect-101 at image edge: (-2,-1)->(2,1)
    int lc0 = c0 - 2, lc1 = c0 - 1;
    if (c0 == 0) { lc0 = 2; lc1 = 1; }
    // Right halo source cols (c+4, c+5); at edge: (512,513)->(510,509)
    int rc0 = c0 + 4, rc1 = c0 + 5;
    if (rc1 >= IMG_W) { rc0 = 510; rc1 = 509; }

    float4 m0, m1, m2, m3;
    float2 l0, l1, l2, l3;
    float2 r0, r1, r2, r3;
    l0 = l1 = l2 = l3 = make_float2(0.f, 0.f);
    r0 = r1 = r2 = r3 = make_float2(0.f, 0.f);

    if (row0 >= 2 && row0 + TILE_H + 2 <= IMG_H) {
        // ---------- interior fast path: pointer increments only ----------
        const float* rp = ip + (size_t)(row0 - 2) * IMG_W;
        loadRow(rp, c0, isL, isR, lc0, lc1, rc0, rc1, m0, l0, r0); rp += IMG_W;
        loadRow(rp, c0, isL, isR, lc0, lc1, rc0, rc1, m1, l1, r1); rp += IMG_W;
        loadRow(rp, c0, isL, isR, lc0, lc1, rc0, rc1, m2, l2, r2); rp += IMG_W;
        loadRow(rp, c0, isL, isR, lc0, lc1, rc0, rc1, m3, l3, r3); rp += IMG_W;

        float* outp = op + (size_t)row0 * IMG_W + c0;
        #pragma unroll 8
        for (int r = 0; r < TILE_H; ++r) {
            float4 n; float2 nl = make_float2(0.f, 0.f), nr = make_float2(0.f, 0.f);
            loadRow(rp, c0, isL, isR, lc0, lc1, rc0, rc1, n, nl, nr); rp += IMG_W;

            float4 v;
            v.x = m0.x + m1.x + m2.x + m3.x + n.x;
            v.y = m0.y + m1.y + m2.y + m3.y + n.y;
            v.z = m0.z + m1.z + m2.z + m3.z + n.z;
            v.w = m0.w + m1.w + m2.w + m3.w + n.w;
            float2 vl = make_float2(0.f, 0.f), vr = make_float2(0.f, 0.f);
            if (isL) { vl.x = l0.x + l1.x + l2.x + l3.x + nl.x;
                       vl.y = l0.y + l1.y + l2.y + l3.y + nl.y; }
            if (isR) { vr.x = r0.x + r1.x + r2.x + r3.x + nr.x;
                       vr.y = r0.y + r1.y + r2.y + r3.y + nr.y; }

            *reinterpret_cast<float4*>(outp) = hstep(v, vl, vr, lane);
            outp += IMG_W;

            m0 = m1; m1 = m2; m2 = m3; m3 = n;
            l0 = l1; l1 = l2; l2 = l3; l3 = nl;
            r0 = r1; r1 = r2; r2 = r3; r3 = nr;
        }
    } else {
        // ---------- boundary blocks: reflected row indexing ----------
        loadRow(ip + (size_t)reflr(row0 - 2) * IMG_W, c0, isL, isR, lc0, lc1, rc0, rc1, m0, l0, r0);
        loadRow(ip + (size_t)reflr(row0 - 1) * IMG_W, c0, isL, isR, lc0, lc1, rc0, rc1, m1, l1, r1);
        loadRow(ip + (size_t)(row0)          * IMG_W, c0, isL, isR, lc0, lc1, rc0, rc1, m2, l2, r2);
        loadRow(ip + (size_t)(row0 + 1)      * IMG_W, c0, isL, isR, lc0, lc1, rc0, rc1, m3, l3, r3);

        #pragma unroll 8
        for (int r = 0; r < TILE_H; ++r) {
            const float* rp = ip + (size_t)reflr(row0 + 2 + r) * IMG_W;
            float4 n; float2 nl = make_float2(0.f, 0.f), nr = make_float2(0.f, 0.f);
            loadRow(rp, c0, isL, isR, lc0, lc1, rc0, rc1, n, nl, nr);

            float4 v;
            v.x = m0.x + m1.x + m2.x + m3.x + n.x;
            v.y = m0.y + m1.y + m2.y + m3.y + n.y;
            v.z = m0.z + m1.z + m2.z + m3.z + n.z;
            v.w = m0.w + m1.w + m2.w + m3.w + n.w;
            float2 vl = make_float2(0.f, 0.f), vr = make_float2(0.f, 0.f);
            if (isL) { vl.x = l0.x + l1.x + l2.x + l3.x + nl.x;
                       vl.y = l0.y + l1.y + l2.y + l3.y + nl.y; }
            if (isR) { vr.x = r0.x + r1.x + r2.x + r3.x + nr.x;
                       vr.y = r0.y + r1.y + r2.y + r3.y + nr.y; }

            *reinterpret_cast<float4*>(op + (size_t)(row0 + r) * IMG_W + c0) = hstep(v, vl, vr, lane);

            m0 = m1; m1 = m2; m2 = m3; m3 = n;
            l0 = l1; l1 = l2; l2 = l3; l3 = nl;
            r0 = r1; r1 = r2; r2 = r3; r3 = nr;
        }
    }
}

extern "C" void kernel_launch(void* const* d_in, const int* in_sizes, int n_in,
                              void* d_out, int out_size)
{
    const float* in  = (const float*)d_in[0];
    float*       out = (float*)d_out;
    int planes = in_sizes[0] / (IMG_H * IMG_W);   // B*C = 96
    dim3 grid(IMG_H / TILE_H, planes);
    smooth5_kernel<<<grid, NTHREADS>>>(in, out);
}

// round 4
// speedup vs baseline: 1.5060x; 1.5060x over previous
#include <cuda_runtime.h>

#define IMG_H 512
#define IMG_W 512
#define TILE_H 16
#define CHUNK 4
#define NCHUNK 4
#define NTHREADS 256
#define VSTRIDE 520   // floats per vsum row: 2 halo + 512 + 2 halo + pad

__device__ __forceinline__ int reflr(int g) {
    // reflect-101: -1 -> 1, -2 -> 2, 512 -> 510, 513 -> 509
    g = g < 0 ? -g : g;
    if (g >= IMG_H) g = 2 * IMG_H - 2 - g;
    return g;
}

__global__ __launch_bounds__(NTHREADS, 8)
void smooth5_kernel(const float* __restrict__ in, float* __restrict__ out)
{
    // Double-buffered 4-row vsum staging: 2 * 4 * 520 * 4B = 16.6 KB
    __shared__ __align__(16) float vs[2][CHUNK * VSTRIDE];

    const int tid   = threadIdx.x;
    const int plane = blockIdx.y;
    const int row0  = blockIdx.x * TILE_H;

    const float* ip = in  + (size_t)plane * (IMG_H * IMG_W);
    float*       op = out + (size_t)plane * (IMG_H * IMG_W);

    // Thread owns columns c0, c0+1 (float2). vsum slot = col + 2.
    // Halo slots 0,1,514,515 = reflect-101 of cols 2,1,510,509: the owning
    // thread just stores one extra copy of a component it already computed.
    const int c0 = 2 * tid;
    int  haloSlot = -1;
    bool haloY    = false;
    if      (tid == 0)   { haloSlot = 1;   haloY = true;  }  // col 1
    else if (tid == 1)   { haloSlot = 0;   haloY = false; }  // col 2
    else if (tid == 254) { haloSlot = 515; haloY = true;  }  // col 509
    else if (tid == 255) { haloSlot = 514; haloY = false; }  // col 510

    const int rs2 = IMG_W / 2;
    const float2* ipc = reinterpret_cast<const float2*>(ip) + tid;

    // Warm-up: vertical window rows row0-2 .. row0+1 (reflected at top edge)
    float2 w0 = ipc[(size_t)reflr(row0 - 2) * rs2];
    float2 w1 = ipc[(size_t)reflr(row0 - 1) * rs2];
    float2 w2 = ipc[(size_t)(row0)          * rs2];
    float2 w3 = ipc[(size_t)(row0 + 1)      * rs2];

    const bool interior = (row0 + TILE_H + 2 <= IMG_H);

    // Prefetch chunk 0 source rows (row0+2 .. row0+5; in-bounds for all blocks)
    float2 nx[CHUNK];
    {
        const float2* rp = ipc + (size_t)(row0 + 2) * rs2;
        nx[0] = rp[0];
        nx[1] = rp[rs2];
        nx[2] = rp[2 * rs2];
        nx[3] = rp[3 * rs2];
    }

    #pragma unroll
    for (int k = 0; k < NCHUNK; ++k) {
        float* buf = vs[k & 1];

        // ---- produce: vertical 5-row sums for rows k*4 .. k*4+3 ----
        #pragma unroll
        for (int j = 0; j < CHUNK; ++j) {
            float2 v;
            v.x = w0.x + w1.x + w2.x + w3.x + nx[j].x;
            v.y = w0.y + w1.y + w2.y + w3.y + nx[j].y;
            *reinterpret_cast<float2*>(&buf[j * VSTRIDE + 2 + c0]) = v;
            if (haloSlot >= 0) buf[j * VSTRIDE + haloSlot] = haloY ? v.y : v.x;
            w0 = w1; w1 = w2; w2 = w3; w3 = nx[j];
        }

        // ---- prefetch chunk k+1 source rows (latency overlaps bar+consume) ----
        if (k < NCHUNK - 1) {
            const int rbase = row0 + 2 + (k + 1) * CHUNK;
            if (interior) {
                const float2* rp = ipc + (size_t)rbase * rs2;
                nx[0] = rp[0];
                nx[1] = rp[rs2];
                nx[2] = rp[2 * rs2];
                nx[3] = rp[3 * rs2];
            } else {
                #pragma unroll
                for (int j = 0; j < CHUNK; ++j)
                    nx[j] = ipc[(size_t)reflr(rbase + j) * rs2];
            }
        }

        __syncthreads();

        // ---- consume: horizontal 5-tap for the 4 staged rows ----
        // 4 rows * 128 float4-groups = 512 tasks; 2 per thread.
        const float inv25 = 1.0f / 25.0f;
        #pragma unroll
        for (int t = 0; t < 2; ++t) {
            int task = tid + t * NTHREADS;
            int rr = task >> 7;      // 0..3
            int q  = task & 127;     // float4 group
            const float* vr = buf + rr * VSTRIDE + 4 * q;
            float4 A  = *reinterpret_cast<const float4*>(vr);
            float4 Bv = *reinterpret_cast<const float4*>(vr + 4);
            float4 o;
            o.x = (A.x + A.y + A.z + A.w + Bv.x) * inv25;
            o.y = (A.y + A.z + A.w + Bv.x + Bv.y) * inv25;
            o.z = (A.z + A.w + Bv.x + Bv.y + Bv.z) * inv25;
            o.w = (A.w + Bv.x + Bv.y + Bv.z + Bv.w) * inv25;
            *reinterpret_cast<float4*>(op + (size_t)(row0 + k * CHUNK + rr) * IMG_W + 4 * q) = o;
        }
        // No second barrier needed: produce(k+1) targets the other buffer, and
        // produce(k+2) (same buffer as consume(k)) is fenced by bar(k+1).
    }
}

extern "C" void kernel_launch(void* const* d_in, const int* in_sizes, int n_in,
                              void* d_out, int out_size)
{
    const float* in  = (const float*)d_in[0];
    float*       out = (float*)d_out;
    int planes = in_sizes[0] / (IMG_H * IMG_W);   // B*C = 96
    dim3 grid(IMG_H / TILE_H, planes);
    smooth5_kernel<<<grid, NTHREADS>>>(in, out);
}